// round 5
// baseline (speedup 1.0000x reference)
#include <cuda_runtime.h>
#include <cstdint>

#define UNITS   512
#define NBATCH  512
#define DIM     64
#define MTILE   128
#define NT      512
#define LDR     72          // row stride (floats) for A tiles / raw-h; 72 % 32 == 8 -> conflict-free frags
#define WLD     72          // col stride for B (weights) layout
#define WSZ     (DIM * WLD) // 4608 floats per weight matrix

// ---- smem float offsets ----
#define SW_OFF    0                   // 6 * 4608  weights, [o][k-interleaved]
#define SX_OFF    (6 * WSZ)           // 128*72    x tile  [r][k-interleaved] (tf32)
#define SH_OFF    (SX_OFF + 128*LDR)  // 128*72    h tile  [r][k-interleaved] (tf32)
#define SHR_OFF   (SH_OFF + 128*LDR)  // 128*72    raw fp32 h [r][c] (exact blend)
#define SB_OFF    (SHR_OFF + 128*LDR) // 4*64 biases: r, z, in, hn
#define SMEM_FLOATS (SB_OFF + 256)

// interleaved k position within an 8-wide k-group: k -> 2*(k&3) + ((k>>2)&1)
// so the mma pair (k=t, k=t+4) sits at {2t, 2t+1}: one LDS.64 per fragment pair.

__device__ __forceinline__ uint32_t f2tf32(float x) {
    uint32_t u;
    asm volatile("cvt.rna.tf32.f32 %0, %1;" : "=r"(u) : "f"(x));
    return u;
}
__device__ __forceinline__ float tf32f(float x) { return __uint_as_float(f2tf32(x)); }

// D += A@B, m16n8k8 tf32. a pair regs: h0 = (row g | k t, k t+4), h1 = (row g+8 | ...)
__device__ __forceinline__ void mma8(float* d, float2 h0, float2 h1, float2 b) {
    asm volatile(
        "mma.sync.aligned.m16n8k8.row.col.f32.tf32.tf32.f32 "
        "{%0,%1,%2,%3}, {%4,%5,%6,%7}, {%8,%9}, {%0,%1,%2,%3};"
        : "+f"(d[0]), "+f"(d[1]), "+f"(d[2]), "+f"(d[3])
        : "r"(__float_as_uint(h0.x)), "r"(__float_as_uint(h1.x)),
          "r"(__float_as_uint(h0.y)), "r"(__float_as_uint(h1.y)),
          "r"(__float_as_uint(b.x)),  "r"(__float_as_uint(b.y)));
}

__device__ __forceinline__ float fast_sigmoid(float v) { return 1.f / (1.f + __expf(-v)); }
__device__ __forceinline__ float fast_tanh(float v)   { return 2.f / (1.f + __expf(-2.f * v)) - 1.f; }

// ---------------------------------------------------------------------------
__global__ void __launch_bounds__(NT, 1)
gru_mma_kernel(const float* __restrict__ x,  const float* __restrict__ h,
               const float* __restrict__ Wir, const float* __restrict__ bir,
               const float* __restrict__ Whr, const float* __restrict__ bhr,
               const float* __restrict__ Wiz, const float* __restrict__ biz,
               const float* __restrict__ Whz, const float* __restrict__ bhz,
               const float* __restrict__ Win, const float* __restrict__ bin,
               const float* __restrict__ Whn, const float* __restrict__ bhn,
               float* __restrict__ out) {
    extern __shared__ float smem[];

    const int u    = blockIdx.x;
    const int tid  = threadIdx.x;
    const int lane = tid & 31;
    const int wid  = tid >> 5;
    const int g    = lane >> 2;   // mma groupID (0..7)
    const int t    = lane & 3;    // thread-in-group
    const int rowBase = (wid & 3) << 5;    // 4 row-warps x 32 rows
    const int colBase = (wid >> 2) << 4;   // 4 col-warps x 16 cols

    // ---- stage 6 weight matrices once: W[k][o] -> smem [o][k-interleaved], tf32 ----
    {
        const float* wsrc[6] = {Wir, Whr, Wiz, Whz, Win, Whn};
        const size_t wOff = (size_t)u * DIM * DIM;
        for (int idx = tid; idx < 6 * DIM * DIM; idx += NT) {
            int gg  = idx >> 12;
            int rem = idx & 4095;
            int i   = rem >> 6;      // k
            int o   = rem & 63;      // fastest -> coalesced gmem
            float v = wsrc[gg][wOff + (size_t)i * DIM + o];
            smem[SW_OFF + gg * WSZ + o * WLD + (i >> 3) * 8 + 2 * (i & 3) + ((i >> 2) & 1)]
                = tf32f(v);
        }
        if (tid < DIM) {
            const size_t bo = (size_t)u * DIM + tid;
            smem[SB_OFF + tid]           = bir[bo] + bhr[bo];
            smem[SB_OFF + 64 + tid]      = biz[bo] + bhz[bo];
            smem[SB_OFF + 128 + tid]     = bin[bo];
            smem[SB_OFF + 192 + tid]     = bhn[bo];
        }
    }
    __syncthreads();

    for (int tile = 0; tile < NBATCH / MTILE; tile++) {
        const int b0 = tile * MTILE;

        // ---- stage x,h (tf32, k-interleaved) + raw h ----
        for (int idx = tid; idx < MTILE * DIM / 4; idx += NT) {
            int r  = idx >> 4;
            int c4 = (idx & 15) * 4;
            size_t ga = ((size_t)(b0 + r) * UNITS + u) * DIM + c4;
            float4 vx = *reinterpret_cast<const float4*>(x + ga);
            float4 vh = *reinterpret_cast<const float4*>(h + ga);
            int base = r * LDR + (c4 >> 3) * 8 + ((c4 >> 2) & 1);
            float* px = smem + SX_OFF + base;
            px[0] = tf32f(vx.x); px[2] = tf32f(vx.y); px[4] = tf32f(vx.z); px[6] = tf32f(vx.w);
            float* ph = smem + SH_OFF + base;
            ph[0] = tf32f(vh.x); ph[2] = tf32f(vh.y); ph[4] = tf32f(vh.z); ph[6] = tf32f(vh.w);
            *reinterpret_cast<float4*>(smem + SHR_OFF + r * LDR + c4) = vh;
        }
        __syncthreads();

        // ---- accumulators pre-loaded with biases ----
        float accR[16], accZ[16], accN[16], accH[16];
#pragma unroll
        for (int ni = 0; ni < 2; ni++) {
            const int c = colBase + ni * 8 + 2 * t;
            float2 bR = *reinterpret_cast<const float2*>(smem + SB_OFF + c);
            float2 bZ = *reinterpret_cast<const float2*>(smem + SB_OFF + 64 + c);
            float2 bN = *reinterpret_cast<const float2*>(smem + SB_OFF + 128 + c);
            float2 bH = *reinterpret_cast<const float2*>(smem + SB_OFF + 192 + c);
#pragma unroll
            for (int mh = 0; mh < 4; mh++) {   // (mi*2+hf)
                const int base = ((mh >> 1) * 2 + ni) * 4 + (mh & 1) * 2;
                accR[base] = bR.x; accR[base + 1] = bR.y;
                accZ[base] = bZ.x; accZ[base + 1] = bZ.y;
                accN[base] = bN.x; accN[base + 1] = bN.y;
                accH[base] = bH.x; accH[base + 1] = bH.y;
            }
        }

        // ---- fused 6-GEMM k-loop ----
#pragma unroll
        for (int kg = 0; kg < 8; kg++) {
            const int fo = kg * 8 + 2 * t;
            float2 ax[2][2], ah[2][2];   // [mi][half(row g / g+8)]
#pragma unroll
            for (int mi = 0; mi < 2; mi++)
#pragma unroll
                for (int hf = 0; hf < 2; hf++) {
                    const int row = rowBase + mi * 16 + hf * 8 + g;
                    ax[mi][hf] = *reinterpret_cast<const float2*>(smem + SX_OFF + row * LDR + fo);
                    ah[mi][hf] = *reinterpret_cast<const float2*>(smem + SH_OFF + row * LDR + fo);
                }
#pragma unroll
            for (int w = 0; w < 6; w++) {
                float* acc = (w < 2) ? accR : (w < 4) ? accZ : (w == 4) ? accN : accH;
                const float2 (*af)[2] = (w & 1) ? ah : ax;
#pragma unroll
                for (int ni = 0; ni < 2; ni++) {
                    float2 b = *reinterpret_cast<const float2*>(
                        smem + SW_OFF + w * WSZ + (colBase + ni * 8 + g) * WLD + fo);
#pragma unroll
                    for (int mi = 0; mi < 2; mi++)
                        mma8(acc + (mi * 2 + ni) * 4, af[mi][0], af[mi][1], b);
                }
            }
        }

        // ---- fused GRU epilogue, direct gmem float2 stores ----
#pragma unroll
        for (int mi = 0; mi < 2; mi++) {
#pragma unroll
            for (int hf = 0; hf < 2; hf++) {
                const int row = rowBase + mi * 16 + hf * 8 + g;
                float* orow = out + ((size_t)(b0 + row) * UNITS + u) * DIM;
#pragma unroll
                for (int ni = 0; ni < 2; ni++) {
                    const int idx = (mi * 2 + ni) * 4 + hf * 2;
                    const int c   = colBase + ni * 8 + 2 * t;
                    float2 hv = *reinterpret_cast<const float2*>(smem + SHR_OFF + row * LDR + c);
                    float2 res;
                    {
                        float r_ = fast_sigmoid(accR[idx]);
                        float z_ = fast_sigmoid(accZ[idx]);
                        float n_ = fast_tanh(accN[idx] + r_ * accH[idx]);
                        res.x = (1.f - z_) * n_ + z_ * hv.x;
                    }
                    {
                        float r_ = fast_sigmoid(accR[idx + 1]);
                        float z_ = fast_sigmoid(accZ[idx + 1]);
                        float n_ = fast_tanh(accN[idx + 1] + r_ * accH[idx + 1]);
                        res.y = (1.f - z_) * n_ + z_ * hv.y;
                    }
                    *reinterpret_cast<float2*>(orow + c) = res;
                }
            }
        }
        __syncthreads();   // SHR/SX/SH reads done before next tile restages
    }
}

// ---------------------------------------------------------------------------
extern "C" void kernel_launch(void* const* d_in, const int* in_sizes, int n_in,
                              void* d_out, int out_size) {
    (void)in_sizes; (void)n_in; (void)out_size;
    const float* x   = (const float*)d_in[0];
    const float* h   = (const float*)d_in[1];
    const float* Wir = (const float*)d_in[2];
    const float* bir = (const float*)d_in[3];
    const float* Whr = (const float*)d_in[4];
    const float* bhr = (const float*)d_in[5];
    const float* Wiz = (const float*)d_in[6];
    const float* biz = (const float*)d_in[7];
    const float* Whz = (const float*)d_in[8];
    const float* bhz = (const float*)d_in[9];
    const float* Win = (const float*)d_in[10];
    const float* bin = (const float*)d_in[11];
    const float* Whn = (const float*)d_in[12];
    const float* bhn = (const float*)d_in[13];
    float* out = (float*)d_out;

    const size_t smemBytes = (size_t)SMEM_FLOATS * sizeof(float);
    cudaFuncSetAttribute(gru_mma_kernel,
                         cudaFuncAttributeMaxDynamicSharedMemorySize, (int)smemBytes);

    gru_mma_kernel<<<UNITS, NT, smemBytes>>>(
        x, h, Wir, bir, Whr, bhr, Wiz, biz, Whz, bhz, Win, bin, Whn, bhn, out);
}

// round 8
// speedup vs baseline: 1.3407x; 1.3407x over previous
#include <cuda_runtime.h>
#include <cstdint>

#define UNITS   512
#define NBATCH  512
#define DIM     64
#define MTILE   128
#define NT      512
#define LD      68            // 64 + 4 pad -> conflict-free fragment LDS (proven in R2)
#define WSZ     (DIM * LD)    // 4352 floats per weight matrix
#define XSZ     (MTILE * LD)  // 8704 floats per activation tile

// ---- smem float offsets (total 43776 floats = 175,104 B; R2 ran with 176,144 B) ----
#define SW_OFF  0              // 6 * WSZ  tf32-rounded weights [k][o], stride LD
#define SX_OFF  (6 * WSZ)      // XSZ      tf32-rounded x tile [r][c], stride LD
#define SH_OFF  (SX_OFF + XSZ) // XSZ      raw fp32 h tile [r][c] (cvt at frag load; exact blend)
#define SB_OFF  (SH_OFF + XSZ) // 4*64 biases: r, z, in, hn
#define SMEM_FLOATS (SB_OFF + 256)

__device__ __forceinline__ uint32_t f2tf32(float x) {
    uint32_t u;
    asm volatile("cvt.rna.tf32.f32 %0, %1;" : "=r"(u) : "f"(x));
    return u;
}

__device__ __forceinline__ void mma8(float* d, const uint32_t* a, const uint32_t* b) {
    asm volatile(
        "mma.sync.aligned.m16n8k8.row.col.f32.tf32.tf32.f32 "
        "{%0,%1,%2,%3}, {%4,%5,%6,%7}, {%8,%9}, {%0,%1,%2,%3};"
        : "+f"(d[0]), "+f"(d[1]), "+f"(d[2]), "+f"(d[3])
        : "r"(a[0]), "r"(a[1]), "r"(a[2]), "r"(a[3]), "r"(b[0]), "r"(b[1]));
}

__device__ __forceinline__ float fast_sigmoid(float v) { return 1.f / (1.f + __expf(-v)); }
__device__ __forceinline__ float fast_tanh(float v)   { return 2.f / (1.f + __expf(-2.f * v)) - 1.f; }

// ---------------------------------------------------------------------------
// 512 threads = 16 warps: 4 row-groups x 4 col-groups; warp tile 32x16.
// One CTA per unit; weights resident in smem; 4 batch tiles of 128 rows.
// ---------------------------------------------------------------------------
__global__ void __launch_bounds__(NT, 1)
gru_mma16_kernel(const float* __restrict__ x,  const float* __restrict__ h,
                 const float* __restrict__ Wir, const float* __restrict__ bir,
                 const float* __restrict__ Whr, const float* __restrict__ bhr,
                 const float* __restrict__ Wiz, const float* __restrict__ biz,
                 const float* __restrict__ Whz, const float* __restrict__ bhz,
                 const float* __restrict__ Win, const float* __restrict__ bin,
                 const float* __restrict__ Whn, const float* __restrict__ bhn,
                 float* __restrict__ out) {
    extern __shared__ float smem[];

    const int u    = blockIdx.x;
    const int tid  = threadIdx.x;
    const int lane = tid & 31;
    const int wid  = tid >> 5;
    const int g    = lane >> 2;            // mma groupID (0..7)
    const int t    = lane & 3;             // thread-in-group
    const int rowBase = (wid & 3) << 5;    // 4 row-warps x 32 rows = 128
    const int colBase = (wid >> 2) << 4;   // 4 col-warps x 16 cols = 64

    // ---- stage 6 weight matrices once (tf32-rounded, [k][o], stride LD) ----
    {
        const float* wsrc[6] = {Wir, Whr, Wiz, Whz, Win, Whn};
        const size_t wOff = (size_t)u * DIM * DIM;
#pragma unroll
        for (int gg = 0; gg < 6; gg++) {
            const float* wp = wsrc[gg] + wOff;
            float* dst = smem + SW_OFF + gg * WSZ;
            for (int i = tid; i < DIM * DIM / 4; i += NT) {
                int r  = i >> 4;
                int c4 = (i & 15) * 4;
                float4 v = *reinterpret_cast<const float4*>(wp + r * DIM + c4);
                float4 o;
                o.x = __uint_as_float(f2tf32(v.x));
                o.y = __uint_as_float(f2tf32(v.y));
                o.z = __uint_as_float(f2tf32(v.z));
                o.w = __uint_as_float(f2tf32(v.w));
                *reinterpret_cast<float4*>(dst + r * LD + c4) = o;
            }
        }
        if (tid < DIM) {
            const size_t bo = (size_t)u * DIM + tid;
            smem[SB_OFF + tid]           = bir[bo] + bhr[bo];
            smem[SB_OFF + 64 + tid]      = biz[bo] + bhz[bo];
            smem[SB_OFF + 128 + tid]     = bin[bo];
            smem[SB_OFF + 192 + tid]     = bhn[bo];
        }
    }
    __syncthreads();

    const float* sX = smem + SX_OFF;
    const float* sH = smem + SH_OFF;
    const float* sW = smem + SW_OFF;

    for (int tile = 0; tile < NBATCH / MTILE; tile++) {
        const int b0 = tile * MTILE;

        // ---- stage x (tf32-rounded) and h (raw fp32) tiles ----
        for (int i = tid; i < MTILE * DIM / 4; i += NT) {
            int r  = i >> 4;
            int c4 = (i & 15) * 4;
            size_t ga = ((size_t)(b0 + r) * UNITS + u) * DIM + c4;
            float4 vx = *reinterpret_cast<const float4*>(x + ga);
            float4 ox;
            ox.x = __uint_as_float(f2tf32(vx.x));
            ox.y = __uint_as_float(f2tf32(vx.y));
            ox.z = __uint_as_float(f2tf32(vx.z));
            ox.w = __uint_as_float(f2tf32(vx.w));
            *reinterpret_cast<float4*>(smem + SX_OFF + r * LD + c4) = ox;
            float4 vh = *reinterpret_cast<const float4*>(h + ga);
            *reinterpret_cast<float4*>(smem + SH_OFF + r * LD + c4) = vh;
        }
        __syncthreads();

        // ---- fused 6-GEMM k-loop: A frags loaded once, used by all 6 ----
        float accR[16], accZ[16], accN[16], accH[16];
#pragma unroll
        for (int i = 0; i < 16; i++) {
            accR[i] = 0.f; accZ[i] = 0.f; accN[i] = 0.f; accH[i] = 0.f;
        }

#pragma unroll
        for (int k0 = 0; k0 < DIM; k0 += 8) {
            uint32_t ax[2][4], ah[2][4];
#pragma unroll
            for (int mi = 0; mi < 2; mi++) {
                const float* ap = sX + (rowBase + mi * 16 + g) * LD + k0 + t;
                ax[mi][0] = __float_as_uint(ap[0]);
                ax[mi][1] = __float_as_uint(ap[8 * LD]);
                ax[mi][2] = __float_as_uint(ap[4]);
                ax[mi][3] = __float_as_uint(ap[8 * LD + 4]);
                const float* hp = sH + (rowBase + mi * 16 + g) * LD + k0 + t;
                ah[mi][0] = f2tf32(hp[0]);
                ah[mi][1] = f2tf32(hp[8 * LD]);
                ah[mi][2] = f2tf32(hp[4]);
                ah[mi][3] = f2tf32(hp[8 * LD + 4]);
            }
#pragma unroll
            for (int ni = 0; ni < 2; ni++) {
                const float* bp = sW + (k0 + t) * LD + colBase + ni * 8 + g;
                uint32_t b[6][2];
#pragma unroll
                for (int w = 0; w < 6; w++) {
                    b[w][0] = __float_as_uint(bp[w * WSZ]);
                    b[w][1] = __float_as_uint(bp[w * WSZ + 4 * LD]);
                }
#pragma unroll
                for (int mi = 0; mi < 2; mi++) {
                    const int o = (mi * 2 + ni) * 4;
                    mma8(accR + o, ax[mi], b[0]);   // x@Wir
                    mma8(accR + o, ah[mi], b[1]);   // h@Whr
                    mma8(accZ + o, ax[mi], b[2]);   // x@Wiz
                    mma8(accZ + o, ah[mi], b[3]);   // h@Whz
                    mma8(accN + o, ax[mi], b[4]);   // x@Win
                    mma8(accH + o, ah[mi], b[5]);   // h@Whn
                }
            }
        }

        // ---- fused GRU epilogue, direct float2 gmem stores ----
#pragma unroll
        for (int mi = 0; mi < 2; mi++) {
#pragma unroll
            for (int ni = 0; ni < 2; ni++) {
                const int base = (mi * 2 + ni) * 4;
                const int col  = colBase + ni * 8 + 2 * t;
#pragma unroll
                for (int half = 0; half < 2; half++) {
                    const int row = rowBase + mi * 16 + g + half * 8;
                    float2 hv = *reinterpret_cast<const float2*>(sH + row * LD + col);
                    float2 res;
                    {
                        const int idx = base + half * 2;
                        float r_ = fast_sigmoid(accR[idx] + smem[SB_OFF + col]);
                        float z_ = fast_sigmoid(accZ[idx] + smem[SB_OFF + 64 + col]);
                        float n_ = fast_tanh(accN[idx] + smem[SB_OFF + 128 + col] +
                                             r_ * (accH[idx] + smem[SB_OFF + 192 + col]));
                        res.x = (1.f - z_) * n_ + z_ * hv.x;
                    }
                    {
                        const int idx = base + half * 2 + 1;
                        float r_ = fast_sigmoid(accR[idx] + smem[SB_OFF + col + 1]);
                        float z_ = fast_sigmoid(accZ[idx] + smem[SB_OFF + 64 + col + 1]);
                        float n_ = fast_tanh(accN[idx] + smem[SB_OFF + 128 + col + 1] +
                                             r_ * (accH[idx] + smem[SB_OFF + 192 + col + 1]));
                        res.y = (1.f - z_) * n_ + z_ * hv.y;
                    }
                    size_t ga = ((size_t)(b0 + row) * UNITS + u) * DIM + col;
                    *reinterpret_cast<float2*>(out + ga) = res;
                }
            }
        }
        __syncthreads();  // sX/sH reads done before next tile restages
    }
}

// ---------------------------------------------------------------------------
extern "C" void kernel_launch(void* const* d_in, const int* in_sizes, int n_in,
                              void* d_out, int out_size) {
    (void)in_sizes; (void)n_in; (void)out_size;
    const float* x   = (const float*)d_in[0];
    const float* h   = (const float*)d_in[1];
    const float* Wir = (const float*)d_in[2];
    const float* bir = (const float*)d_in[3];
    const float* Whr = (const float*)d_in[4];
    const float* bhr = (const float*)d_in[5];
    const float* Wiz = (const float*)d_in[6];
    const float* biz = (const float*)d_in[7];
    const float* Whz = (const float*)d_in[8];
    const float* bhz = (const float*)d_in[9];
    const float* Win = (const float*)d_in[10];
    const float* bin = (const float*)d_in[11];
    const float* Whn = (const float*)d_in[12];
    const float* bhn = (const float*)d_in[13];
    float* out = (float*)d_out;

    const size_t smemBytes = (size_t)SMEM_FLOATS * sizeof(float);
    cudaFuncSetAttribute(gru_mma16_kernel,
                         cudaFuncAttributeMaxDynamicSharedMemorySize, (int)smemBytes);

    gru_mma16_kernel<<<UNITS, NT, smemBytes>>>(
        x, h, Wir, bir, Whr, bhr, Wiz, biz, Whz, bhz, Win, bin, Whn, bhn, out);
}

// round 9
// speedup vs baseline: 1.3849x; 1.0329x over previous
#include <cuda_runtime.h>
#include <cstdint>

#define UNITS   512
#define NBATCH  512
#define DIM     64
#define MTILE   128
#define NT      512
#define LD      68            // stride: 68 % 32 == 4 -> banks 4g+t all-distinct for [row][k] frags
#define WSZ     (DIM * LD)    // 4352 floats per weight matrix
#define XSZ     (MTILE * LD)  // 8704 floats per activation tile

// ---- smem float offsets (175,104 B total; same envelope as passing R8) ----
#define SW_OFF  0              // 6 * WSZ  tf32-rounded weights TRANSPOSED [o][k], stride LD
#define SX_OFF  (6 * WSZ)      // XSZ      tf32-rounded x tile [r][c], stride LD
#define SH_OFF  (SX_OFF + XSZ) // XSZ      raw fp32 h tile [r][c] (cvt at frag load; exact blend)
#define SB_OFF  (SH_OFF + XSZ) // 4*64 biases: r, z, in, hn
#define SMEM_FLOATS (SB_OFF + 256)

__device__ __forceinline__ uint32_t f2tf32(float x) {
    uint32_t u;
    asm volatile("cvt.rna.tf32.f32 %0, %1;" : "=r"(u) : "f"(x));
    return u;
}

__device__ __forceinline__ void mma8(float* d, const uint32_t* a, const uint32_t* b) {
    asm volatile(
        "mma.sync.aligned.m16n8k8.row.col.f32.tf32.tf32.f32 "
        "{%0,%1,%2,%3}, {%4,%5,%6,%7}, {%8,%9}, {%0,%1,%2,%3};"
        : "+f"(d[0]), "+f"(d[1]), "+f"(d[2]), "+f"(d[3])
        : "r"(a[0]), "r"(a[1]), "r"(a[2]), "r"(a[3]), "r"(b[0]), "r"(b[1]));
}

__device__ __forceinline__ float fast_sigmoid(float v) { return 1.f / (1.f + __expf(-v)); }
__device__ __forceinline__ float fast_tanh(float v)   { return 2.f / (1.f + __expf(-2.f * v)) - 1.f; }

// ---------------------------------------------------------------------------
// 512 threads = 16 warps: 4 row-groups x 4 col-groups; warp tile 32x16.
// One CTA per unit; weights resident in smem (transposed, conflict-free);
// 4 batch tiles of 128 rows.
// ---------------------------------------------------------------------------
__global__ void __launch_bounds__(NT, 1)
gru_mma16t_kernel(const float* __restrict__ x,  const float* __restrict__ h,
                  const float* __restrict__ Wir, const float* __restrict__ bir,
                  const float* __restrict__ Whr, const float* __restrict__ bhr,
                  const float* __restrict__ Wiz, const float* __restrict__ biz,
                  const float* __restrict__ Whz, const float* __restrict__ bhz,
                  const float* __restrict__ Win, const float* __restrict__ bin,
                  const float* __restrict__ Whn, const float* __restrict__ bhn,
                  float* __restrict__ out) {
    extern __shared__ float smem[];

    const int u    = blockIdx.x;
    const int tid  = threadIdx.x;
    const int lane = tid & 31;
    const int wid  = tid >> 5;
    const int g    = lane >> 2;            // mma groupID (0..7)
    const int t    = lane & 3;             // thread-in-group
    const int rowBase = (wid & 3) << 5;    // 4 row-warps x 32 rows = 128
    const int colBase = (wid >> 2) << 4;   // 4 col-warps x 16 cols = 64

    // ---- stage 6 weight matrices once, TRANSPOSED: W[k][o] -> sW[o*LD + k] ----
    {
        const float* wsrc[6] = {Wir, Whr, Wiz, Whz, Win, Whn};
        const size_t wOff = (size_t)u * DIM * DIM;
#pragma unroll
        for (int gg = 0; gg < 6; gg++) {
            const float* wp = wsrc[gg] + wOff;
            float* dst = smem + SW_OFF + gg * WSZ;
            for (int i = tid; i < DIM * DIM / 4; i += NT) {
                int k  = i >> 4;             // gmem row (input dim)
                int o4 = (i & 15) * 4;       // gmem col block (output dim) -> coalesced read
                float4 v = *reinterpret_cast<const float4*>(wp + k * DIM + o4);
                dst[(o4 + 0) * LD + k] = __uint_as_float(f2tf32(v.x));
                dst[(o4 + 1) * LD + k] = __uint_as_float(f2tf32(v.y));
                dst[(o4 + 2) * LD + k] = __uint_as_float(f2tf32(v.z));
                dst[(o4 + 3) * LD + k] = __uint_as_float(f2tf32(v.w));
            }
        }
        if (tid < DIM) {
            const size_t bo = (size_t)u * DIM + tid;
            smem[SB_OFF + tid]           = bir[bo] + bhr[bo];
            smem[SB_OFF + 64 + tid]      = biz[bo] + bhz[bo];
            smem[SB_OFF + 128 + tid]     = bin[bo];
            smem[SB_OFF + 192 + tid]     = bhn[bo];
        }
    }
    __syncthreads();

    const float* sX = smem + SX_OFF;
    const float* sH = smem + SH_OFF;
    const float* sW = smem + SW_OFF;

    for (int tile = 0; tile < NBATCH / MTILE; tile++) {
        const int b0 = tile * MTILE;

        // ---- stage x (tf32-rounded) and h (raw fp32) tiles ----
        for (int i = tid; i < MTILE * DIM / 4; i += NT) {
            int r  = i >> 4;
            int c4 = (i & 15) * 4;
            size_t ga = ((size_t)(b0 + r) * UNITS + u) * DIM + c4;
            float4 vx = *reinterpret_cast<const float4*>(x + ga);
            float4 ox;
            ox.x = __uint_as_float(f2tf32(vx.x));
            ox.y = __uint_as_float(f2tf32(vx.y));
            ox.z = __uint_as_float(f2tf32(vx.z));
            ox.w = __uint_as_float(f2tf32(vx.w));
            *reinterpret_cast<float4*>(smem + SX_OFF + r * LD + c4) = ox;
            float4 vh = *reinterpret_cast<const float4*>(h + ga);
            *reinterpret_cast<float4*>(smem + SH_OFF + r * LD + c4) = vh;
        }
        __syncthreads();

        // ---- fused 6-GEMM k-loop: A frags loaded once, used by all 6 ----
        float accR[16], accZ[16], accN[16], accH[16];
#pragma unroll
        for (int i = 0; i < 16; i++) {
            accR[i] = 0.f; accZ[i] = 0.f; accN[i] = 0.f; accH[i] = 0.f;
        }

#pragma unroll
        for (int k0 = 0; k0 < DIM; k0 += 8) {
            uint32_t ax[2][4], ah[2][4];
#pragma unroll
            for (int mi = 0; mi < 2; mi++) {
                const float* ap = sX + (rowBase + mi * 16 + g) * LD + k0 + t;
                ax[mi][0] = __float_as_uint(ap[0]);
                ax[mi][1] = __float_as_uint(ap[8 * LD]);
                ax[mi][2] = __float_as_uint(ap[4]);
                ax[mi][3] = __float_as_uint(ap[8 * LD + 4]);
                const float* hp = sH + (rowBase + mi * 16 + g) * LD + k0 + t;
                ah[mi][0] = f2tf32(hp[0]);
                ah[mi][1] = f2tf32(hp[8 * LD]);
                ah[mi][2] = f2tf32(hp[4]);
                ah[mi][3] = f2tf32(hp[8 * LD + 4]);
            }
#pragma unroll
            for (int ni = 0; ni < 2; ni++) {
                // transposed weights: row = output col (stride LD), k contiguous
                // bank = 4g + t -> all 32 lanes distinct -> conflict-free
                const float* bp = sW + (colBase + ni * 8 + g) * LD + k0 + t;
                uint32_t b[6][2];
#pragma unroll
                for (int w = 0; w < 6; w++) {
                    b[w][0] = __float_as_uint(bp[w * WSZ]);
                    b[w][1] = __float_as_uint(bp[w * WSZ + 4]);
                }
#pragma unroll
                for (int mi = 0; mi < 2; mi++) {
                    const int o = (mi * 2 + ni) * 4;
                    mma8(accR + o, ax[mi], b[0]);   // x@Wir
                    mma8(accR + o, ah[mi], b[1]);   // h@Whr
                    mma8(accZ + o, ax[mi], b[2]);   // x@Wiz
                    mma8(accZ + o, ah[mi], b[3]);   // h@Whz
                    mma8(accN + o, ax[mi], b[4]);   // x@Win
                    mma8(accH + o, ah[mi], b[5]);   // h@Whn
                }
            }
        }

        // ---- fused GRU epilogue, direct float2 gmem stores ----
#pragma unroll
        for (int mi = 0; mi < 2; mi++) {
#pragma unroll
            for (int ni = 0; ni < 2; ni++) {
                const int base = (mi * 2 + ni) * 4;
                const int col  = colBase + ni * 8 + 2 * t;
#pragma unroll
                for (int half = 0; half < 2; half++) {
                    const int row = rowBase + mi * 16 + g + half * 8;
                    float2 hv = *reinterpret_cast<const float2*>(sH + row * LD + col);
                    float2 res;
                    {
                        const int idx = base + half * 2;
                        float r_ = fast_sigmoid(accR[idx] + smem[SB_OFF + col]);
                        float z_ = fast_sigmoid(accZ[idx] + smem[SB_OFF + 64 + col]);
                        float n_ = fast_tanh(accN[idx] + smem[SB_OFF + 128 + col] +
                                             r_ * (accH[idx] + smem[SB_OFF + 192 + col]));
                        res.x = (1.f - z_) * n_ + z_ * hv.x;
                    }
                    {
                        const int idx = base + half * 2 + 1;
                        float r_ = fast_sigmoid(accR[idx] + smem[SB_OFF + col + 1]);
                        float z_ = fast_sigmoid(accZ[idx] + smem[SB_OFF + 64 + col + 1]);
                        float n_ = fast_tanh(accN[idx] + smem[SB_OFF + 128 + col + 1] +
                                             r_ * (accH[idx] + smem[SB_OFF + 192 + col + 1]));
                        res.y = (1.f - z_) * n_ + z_ * hv.y;
                    }
                    size_t ga = ((size_t)(b0 + row) * UNITS + u) * DIM + col;
                    *reinterpret_cast<float2*>(out + ga) = res;
                }
            }
        }
        __syncthreads();  // sX/sH reads done before next tile restages
    }
}

// ---------------------------------------------------------------------------
extern "C" void kernel_launch(void* const* d_in, const int* in_sizes, int n_in,
                              void* d_out, int out_size) {
    (void)in_sizes; (void)n_in; (void)out_size;
    const float* x   = (const float*)d_in[0];
    const float* h   = (const float*)d_in[1];
    const float* Wir = (const float*)d_in[2];
    const float* bir = (const float*)d_in[3];
    const float* Whr = (const float*)d_in[4];
    const float* bhr = (const float*)d_in[5];
    const float* Wiz = (const float*)d_in[6];
    const float* biz = (const float*)d_in[7];
    const float* Whz = (const float*)d_in[8];
    const float* bhz = (const float*)d_in[9];
    const float* Win = (const float*)d_in[10];
    const float* bin = (const float*)d_in[11];
    const float* Whn = (const float*)d_in[12];
    const float* bhn = (const float*)d_in[13];
    float* out = (float*)d_out;

    const size_t smemBytes = (size_t)SMEM_FLOATS * sizeof(float);
    cudaFuncSetAttribute(gru_mma16t_kernel,
                         cudaFuncAttributeMaxDynamicSharedMemorySize, (int)smemBytes);

    gru_mma16t_kernel<<<UNITS, NT, smemBytes>>>(
        x, h, Wir, bir, Whr, bhr, Wiz, biz, Whz, bhz, Win, bin, Whn, bhn, out);
}

// round 10
// speedup vs baseline: 1.5442x; 1.1150x over previous
#include <cuda_runtime.h>
#include <cstdint>

#define UNITS   512
#define NBATCH  512
#define DIM     64
#define MT      64            // batch tile (double-buffered)
#define NTILES  (NBATCH / MT) // 8
#define NT      512
#define LD      68            // stride: bank(4g+t) all-distinct for fragment LDS
#define WSZ     (DIM * LD)    // 4352 floats per weight matrix
#define TSZ     (MT * LD)     // 4352 floats per activation tile buffer

// ---- smem float offsets (total 43776 floats = 175,104 B; proven envelope) ----
#define SW_OFF  0                     // 6*WSZ  tf32 weights TRANSPOSED [o][k], stride LD
#define SXB_OFF (6 * WSZ)             // 2*TSZ  raw x tile, double-buffered
#define SHB_OFF (SXB_OFF + 2 * TSZ)   // 2*TSZ  raw h tile, double-buffered
#define SB_OFF  (SHB_OFF + 2 * TSZ)   // 4*64 biases: r, z, in, hn
#define SMEM_FLOATS (SB_OFF + 256)

__device__ __forceinline__ uint32_t f2tf32(float x) {
    uint32_t u;
    asm volatile("cvt.rna.tf32.f32 %0, %1;" : "=r"(u) : "f"(x));
    return u;
}

__device__ __forceinline__ void mma8(float* d, const uint32_t* a, const uint32_t* b) {
    asm volatile(
        "mma.sync.aligned.m16n8k8.row.col.f32.tf32.tf32.f32 "
        "{%0,%1,%2,%3}, {%4,%5,%6,%7}, {%8,%9}, {%0,%1,%2,%3};"
        : "+f"(d[0]), "+f"(d[1]), "+f"(d[2]), "+f"(d[3])
        : "r"(a[0]), "r"(a[1]), "r"(a[2]), "r"(a[3]), "r"(b[0]), "r"(b[1]));
}

__device__ __forceinline__ float fast_sigmoid(float v) { return 1.f / (1.f + __expf(-v)); }
__device__ __forceinline__ float fast_tanh(float v)   { return 2.f / (1.f + __expf(-2.f * v)) - 1.f; }

// ---------------------------------------------------------------------------
// 512 threads = 16 warps: 4 row-groups x 4 col-groups; warp tile 16x16.
// One CTA per unit. Weights resident (transposed, conflict-free). Batch
// processed as 8 tiles of 64 rows, cp.async double-buffered: prefetch t+1
// overlaps compute t. tf32 conversion at fragment-load time.
// ---------------------------------------------------------------------------
__global__ void __launch_bounds__(NT, 1)
gru_mma_pipe_kernel(const float* __restrict__ x,  const float* __restrict__ h,
                    const float* __restrict__ Wir, const float* __restrict__ bir,
                    const float* __restrict__ Whr, const float* __restrict__ bhr,
                    const float* __restrict__ Wiz, const float* __restrict__ biz,
                    const float* __restrict__ Whz, const float* __restrict__ bhz,
                    const float* __restrict__ Win, const float* __restrict__ bin,
                    const float* __restrict__ Whn, const float* __restrict__ bhn,
                    float* __restrict__ out) {
    extern __shared__ float smem[];

    const int u    = blockIdx.x;
    const int tid  = threadIdx.x;
    const int lane = tid & 31;
    const int wid  = tid >> 5;
    const int g    = lane >> 2;            // mma groupID (0..7)
    const int t    = lane & 3;             // thread-in-group
    const int rowBase = (wid & 3) << 4;    // 4 row-warps x 16 rows = 64
    const int colBase = (wid >> 2) << 4;   // 4 col-warps x 16 cols = 64

    const uint32_t sxb_u32 = (uint32_t)__cvta_generic_to_shared(smem + SXB_OFF);
    const uint32_t shb_u32 = (uint32_t)__cvta_generic_to_shared(smem + SHB_OFF);

    // prefetch tile 0 into buffer 0 (overlaps the weight prologue below)
    {
#pragma unroll
        for (int it = 0; it < 2; it++) {
            int cidx = tid + it * NT;
            int r  = cidx >> 4;
            int c4 = (cidx & 15) * 4;
            size_t ga = ((size_t)r * UNITS + u) * DIM + c4;
            uint32_t off = (uint32_t)(r * LD + c4) * 4;
            asm volatile("cp.async.cg.shared.global [%0], [%1], 16;"
                         :: "r"(sxb_u32 + off), "l"(x + ga));
            asm volatile("cp.async.cg.shared.global [%0], [%1], 16;"
                         :: "r"(shb_u32 + off), "l"(h + ga));
        }
        asm volatile("cp.async.commit_group;");
    }

    // ---- stage 6 weight matrices once, TRANSPOSED: W[k][o] -> sW[o*LD + k] ----
    {
        const float* wsrc[6] = {Wir, Whr, Wiz, Whz, Win, Whn};
        const size_t wOff = (size_t)u * DIM * DIM;
#pragma unroll
        for (int gg = 0; gg < 6; gg++) {
            const float* wp = wsrc[gg] + wOff;
            float* dst = smem + SW_OFF + gg * WSZ;
            for (int i = tid; i < DIM * DIM / 4; i += NT) {
                int k  = i >> 4;
                int o4 = (i & 15) * 4;
                float4 v = *reinterpret_cast<const float4*>(wp + k * DIM + o4);
                dst[(o4 + 0) * LD + k] = __uint_as_float(f2tf32(v.x));
                dst[(o4 + 1) * LD + k] = __uint_as_float(f2tf32(v.y));
                dst[(o4 + 2) * LD + k] = __uint_as_float(f2tf32(v.z));
                dst[(o4 + 3) * LD + k] = __uint_as_float(f2tf32(v.w));
            }
        }
        if (tid < DIM) {
            const size_t bo = (size_t)u * DIM + tid;
            smem[SB_OFF + tid]           = bir[bo] + bhr[bo];
            smem[SB_OFF + 64 + tid]      = biz[bo] + bhz[bo];
            smem[SB_OFF + 128 + tid]     = bin[bo];
            smem[SB_OFF + 192 + tid]     = bhn[bo];
        }
    }

    const float* sW = smem + SW_OFF;

    for (int tile = 0; tile < NTILES; tile++) {
        const int buf = tile & 1;
        const int b0  = tile * MT;

        // tile's data landed (this thread) -> barrier makes it CTA-visible and
        // confirms everyone is done computing on the buffer we prefetch into
        asm volatile("cp.async.wait_group 0;" ::: "memory");
        __syncthreads();

        if (tile + 1 < NTILES) {
            const int b0n = b0 + MT;
            const uint32_t boff = (uint32_t)((buf ^ 1) * TSZ) * 4;
#pragma unroll
            for (int it = 0; it < 2; it++) {
                int cidx = tid + it * NT;
                int r  = cidx >> 4;
                int c4 = (cidx & 15) * 4;
                size_t ga = ((size_t)(b0n + r) * UNITS + u) * DIM + c4;
                uint32_t off = boff + (uint32_t)(r * LD + c4) * 4;
                asm volatile("cp.async.cg.shared.global [%0], [%1], 16;"
                             :: "r"(sxb_u32 + off), "l"(x + ga));
                asm volatile("cp.async.cg.shared.global [%0], [%1], 16;"
                             :: "r"(shb_u32 + off), "l"(h + ga));
            }
            asm volatile("cp.async.commit_group;");
        }

        const float* sXt = smem + SXB_OFF + buf * TSZ;
        const float* sHt = smem + SHB_OFF + buf * TSZ;

        // ---- fused 6-GEMM k-loop (cvt-at-load, A frags shared by all 6) ----
        float accR[8], accZ[8], accN[8], accH[8];
#pragma unroll
        for (int i = 0; i < 8; i++) {
            accR[i] = 0.f; accZ[i] = 0.f; accN[i] = 0.f; accH[i] = 0.f;
        }

#pragma unroll
        for (int k0 = 0; k0 < DIM; k0 += 8) {
            uint32_t ax[4], ah[4];
            {
                const float* ap = sXt + (rowBase + g) * LD + k0 + t;
                ax[0] = f2tf32(ap[0]);
                ax[1] = f2tf32(ap[8 * LD]);
                ax[2] = f2tf32(ap[4]);
                ax[3] = f2tf32(ap[8 * LD + 4]);
                const float* hp = sHt + (rowBase + g) * LD + k0 + t;
                ah[0] = f2tf32(hp[0]);
                ah[1] = f2tf32(hp[8 * LD]);
                ah[2] = f2tf32(hp[4]);
                ah[3] = f2tf32(hp[8 * LD + 4]);
            }
#pragma unroll
            for (int ni = 0; ni < 2; ni++) {
                const float* bp = sW + (colBase + ni * 8 + g) * LD + k0 + t;
                uint32_t b[6][2];
#pragma unroll
                for (int w = 0; w < 6; w++) {
                    b[w][0] = __float_as_uint(bp[w * WSZ]);
                    b[w][1] = __float_as_uint(bp[w * WSZ + 4]);
                }
                const int o = ni * 4;
                mma8(accR + o, ax, b[0]);   // x@Wir
                mma8(accR + o, ah, b[1]);   // h@Whr
                mma8(accZ + o, ax, b[2]);   // x@Wiz
                mma8(accZ + o, ah, b[3]);   // h@Whz
                mma8(accN + o, ax, b[4]);   // x@Win
                mma8(accH + o, ah, b[5]);   // h@Whn
            }
        }

        // ---- fused GRU epilogue, direct float2 gmem stores ----
#pragma unroll
        for (int ni = 0; ni < 2; ni++) {
            const int col = colBase + ni * 8 + 2 * t;
#pragma unroll
            for (int half = 0; half < 2; half++) {
                const int row = rowBase + g + half * 8;
                float2 hv = *reinterpret_cast<const float2*>(sHt + row * LD + col);
                float2 res;
                {
                    const int idx = ni * 4 + half * 2;
                    float r_ = fast_sigmoid(accR[idx] + smem[SB_OFF + col]);
                    float z_ = fast_sigmoid(accZ[idx] + smem[SB_OFF + 64 + col]);
                    float n_ = fast_tanh(accN[idx] + smem[SB_OFF + 128 + col] +
                                         r_ * (accH[idx] + smem[SB_OFF + 192 + col]));
                    res.x = (1.f - z_) * n_ + z_ * hv.x;
                }
                {
                    const int idx = ni * 4 + half * 2 + 1;
                    float r_ = fast_sigmoid(accR[idx] + smem[SB_OFF + col + 1]);
                    float z_ = fast_sigmoid(accZ[idx] + smem[SB_OFF + 64 + col + 1]);
                    float n_ = fast_tanh(accN[idx] + smem[SB_OFF + 128 + col + 1] +
                                         r_ * (accH[idx] + smem[SB_OFF + 192 + col + 1]));
                    res.y = (1.f - z_) * n_ + z_ * hv.y;
                }
                size_t ga = ((size_t)(b0 + row) * UNITS + u) * DIM + col;
                *reinterpret_cast<float2*>(out + ga) = res;
            }
        }
    }
}

// ---------------------------------------------------------------------------
extern "C" void kernel_launch(void* const* d_in, const int* in_sizes, int n_in,
                              void* d_out, int out_size) {
    (void)in_sizes; (void)n_in; (void)out_size;
    const float* x   = (const float*)d_in[0];
    const float* h   = (const float*)d_in[1];
    const float* Wir = (const float*)d_in[2];
    const float* bir = (const float*)d_in[3];
    const float* Whr = (const float*)d_in[4];
    const float* bhr = (const float*)d_in[5];
    const float* Wiz = (const float*)d_in[6];
    const float* biz = (const float*)d_in[7];
    const float* Whz = (const float*)d_in[8];
    const float* bhz = (const float*)d_in[9];
    const float* Win = (const float*)d_in[10];
    const float* bin = (const float*)d_in[11];
    const float* Whn = (const float*)d_in[12];
    const float* bhn = (const float*)d_in[13];
    float* out = (float*)d_out;

    const size_t smemBytes = (size_t)SMEM_FLOATS * sizeof(float);
    cudaFuncSetAttribute(gru_mma_pipe_kernel,
                         cudaFuncAttributeMaxDynamicSharedMemorySize, (int)smemBytes);

    gru_mma_pipe_kernel<<<UNITS, NT, smemBytes>>>(
        x, h, Wir, bir, Whr, bhr, Wiz, biz, Whz, bhz, Win, bin, Whn, bhn, out);
}